// round 15
// baseline (speedup 1.0000x reference)
#include <cuda_runtime.h>
#include <cuda_fp16.h>
#include <cstdint>

// Problem dims (fixed by dataset)
constexpr int Bb = 4;      // batch
constexpr int Nq = 4096;   // H*W
constexpr int C  = 256;    // channels
constexpr int CK = 32;     // key/query channels

// Scratch in __device__ globals (allocation-free rule)
__device__ __half g_f [(size_t)Bb * Nq * CK];            // keys   (fp16 hi)
__device__ __half g_fl[(size_t)Bb * Nq * CK];            // keys   (fp16 lo residual)
__device__ __half g_g [(size_t)Bb * Nq * CK];            // queries(fp16 hi)
__device__ __half g_gl[(size_t)Bb * Nq * CK];            // queries(fp16 lo residual)
__device__ __half g_hT[(size_t)Bb * C * Nq];             // values, transposed, fp16
__device__ float  g_s [(size_t)Bb * Nq * Nq];            // raw scores fp32 (256 MB)
__device__ __half g_WT  [320 * 256];                     // [Wf|Wg|Wh]^T fp16 hi
__device__ __half g_WTlo[64 * 256];                      // lo residual for f,g cols
__device__ unsigned int g_rowmaxE[Bb * Nq];              // encoded row maxes

__device__ __forceinline__ uint32_t smem_u32(const void* p) {
    return (uint32_t)__cvta_generic_to_shared(p);
}
__device__ __forceinline__ void cp16(uint32_t s, const void* g) {
    asm volatile("cp.async.cg.shared.global [%0], [%1], 16;" :: "r"(s), "l"(g));
}
__device__ __forceinline__ void cp_commit() {
    asm volatile("cp.async.commit_group;" ::: "memory");
}
__device__ __forceinline__ uint32_t pack2(__half a, __half b) {
    __half2 h = __halves2half2(a, b);
    return *(uint32_t*)&h;
}
__device__ __forceinline__ void mma_f16(float* d, const uint32_t* a, const uint32_t* b) {
    asm volatile(
        "mma.sync.aligned.m16n8k16.row.col.f32.f16.f16.f32 "
        "{%0,%1,%2,%3}, {%4,%5,%6,%7}, {%8,%9}, {%0,%1,%2,%3};"
        : "+f"(d[0]), "+f"(d[1]), "+f"(d[2]), "+f"(d[3])
        : "r"(a[0]), "r"(a[1]), "r"(a[2]), "r"(a[3]), "r"(b[0]), "r"(b[1]));
}
__device__ __forceinline__ void ldsm4(uint32_t* r, uint32_t a) {
    asm volatile("ldmatrix.sync.aligned.m8n8.x4.shared.b16 {%0,%1,%2,%3}, [%4];"
        : "=r"(r[0]), "=r"(r[1]), "=r"(r[2]), "=r"(r[3]) : "r"(a));
}
__device__ __forceinline__ void ldsm2(uint32_t* r, uint32_t a) {
    asm volatile("ldmatrix.sync.aligned.m8n8.x2.shared.b16 {%0,%1}, [%2];"
        : "=r"(r[0]), "=r"(r[1]) : "r"(a));
}
// monotone float<->uint encoding for atomicMax over signed floats
__device__ __forceinline__ uint32_t fenc(float f) {
    uint32_t u = __float_as_uint(f);
    return (u & 0x80000000u) ? ~u : (u | 0x80000000u);
}
__device__ __forceinline__ float fdec(uint32_t e) {
    uint32_t u = (e & 0x80000000u) ? (e & 0x7fffffffu) : ~e;
    return __uint_as_float(u);
}

// ===========================================================================
// Kernel 0: W pre-transpose + fp16 hi/lo pre-split; init row-max table.
// ===========================================================================
__global__ void wtrans_kernel(const float* __restrict__ Wf,
                              const float* __restrict__ Wg,
                              const float* __restrict__ Wh) {
    int idx = blockIdx.x * 256 + threadIdx.x;       // 320*256 total
    if (idx < Bb * Nq) g_rowmaxE[idx] = 0u;         // < any real encoded value
    int n = idx >> 8, k = idx & 255;
    float w;
    if (n < 32)       w = Wf[k * CK + n];
    else if (n < 64)  w = Wg[k * CK + (n - 32)];
    else              w = Wh[k * C + (n - 64)];
    __half hi = __float2half_rn(w);
    g_WT[n * 256 + k] = hi;
    if (n < 64)
        g_WTlo[n * 256 + k] = __float2half_rn(w - __half2float(hi));
}

// ===========================================================================
// Kernel 1: fused projections, fp16 mma, PIPELINED (pv-style).
// CTA 128 rows x 320 cols, K=256 in 8 chunks of 32.
// 512 threads, 16 warps (4m x 4n), warp tile 32x80.
// X: LDG 2 ahead -> cvt hi/lo + STS 1 ahead (2 smem stages).
// W: 3-stage cp.async ring, wait_group 1 per iter.
// Producer interleaved between the two ks mma halves.
// ===========================================================================
constexpr int PJ_XST  = 128 * 80;                       // 10240 B per X buf
constexpr int PJ_W_OFF = 4 * PJ_XST;                    // 40960 (XH0,XL0,XH1,XL1)
constexpr int PJ_WST  = 320 * 80 + 64 * 80;             // 30720 per W stage
constexpr int PJ_SMEM = PJ_W_OFF + 3 * PJ_WST;          // 133120 B

__global__ __launch_bounds__(512, 1)
void proj_kernel(const float* __restrict__ x,
                 const float* __restrict__ bfv, const float* __restrict__ bgv,
                 const float* __restrict__ bhv) {
    extern __shared__ char dsm[];
    const uint32_t base = smem_u32(dsm);

    const int t = threadIdx.x;
    const int lane = t & 31, wid = t >> 5;
    const int wm = wid >> 2, wn = wid & 3;      // 4(M) x 4(N)
    const int rowbase = blockIdx.x * 128;

    const int arow   = (lane & 7) + ((lane >> 3) & 1) * 8;
    const int acol16 = (lane >> 4) * 16;
    const int brow2  = lane & 7;
    const int bcol16 = ((lane >> 3) & 1) * 16;

    float acc[2][10][4] = {};
    float4 va[2];

    // X loader: 128 rows x 32 floats = 1024 float4, 2 per thread
    auto ldgX = [&](int ch) {
        #pragma unroll
        for (int i = 0; i < 2; i++) {
            int idx = t + i * 512;
            int r = idx >> 3, c4 = (idx & 7) * 4;
            va[i] = *(const float4*)(x + (size_t)(rowbase + r) * C + ch * 32 + c4);
        }
    };
    auto stsX = [&](int ch) {
        char* XH = dsm + (ch & 1) * 2 * PJ_XST;
        char* XL = XH + PJ_XST;
        #pragma unroll
        for (int i = 0; i < 2; i++) {
            int idx = t + i * 512;
            int r = idx >> 3, c4 = (idx & 7) * 4;
            float f[4] = {va[i].x, va[i].y, va[i].z, va[i].w};
            __half h[4], l[4];
            #pragma unroll
            for (int e = 0; e < 4; e++) {
                h[e] = __float2half_rn(f[e]);
                l[e] = __float2half_rn(f[e] - __half2float(h[e]));
            }
            uint2 uh, ul;
            uh.x = pack2(h[0], h[1]); uh.y = pack2(h[2], h[3]);
            ul.x = pack2(l[0], l[1]); ul.y = pack2(l[2], l[3]);
            *(uint2*)(XH + r * 80 + c4 * 2) = uh;
            *(uint2*)(XL + r * 80 + c4 * 2) = ul;
        }
    };
    // W loader: hi 320x32 halves = 1280 cp16 (3 rounds, guarded) + lo 256 cp16
    auto cpW = [&](int ch) {
        uint32_t WH = base + PJ_W_OFF + (ch % 3) * PJ_WST;
        uint32_t WL = WH + 320 * 80;
        #pragma unroll
        for (int i = 0; i < 3; i++) {
            int idx = t + i * 512;
            if (idx < 1280) {
                int r = idx >> 2, seg = idx & 3;
                cp16(WH + r * 80 + seg * 16, g_WT + r * 256 + ch * 32 + seg * 8);
            }
        }
        if (t < 256) {
            int r = t >> 2, seg = t & 3;
            cp16(WL + r * 80 + seg * 16, g_WTlo + r * 256 + ch * 32 + seg * 8);
        }
        cp_commit();
    };

    // prologue
    cpW(0); cpW(1);
    ldgX(0);
    stsX(0);
    ldgX(1);
    asm volatile("cp.async.wait_group 1;" ::: "memory");   // W0 ready
    __syncthreads();

    for (int ch = 0; ch < 8; ch++) {
        if (ch + 2 < 8) cpW(ch + 2);   // stage (ch+2)%3, freed by last barrier

        const uint32_t XHU = base + (ch & 1) * 2 * PJ_XST;
        const uint32_t XLU = XHU + PJ_XST;
        const uint32_t WHU = base + PJ_W_OFF + (ch % 3) * PJ_WST;
        const uint32_t WLU = WHU + 320 * 80;

        // ---- mma ks = 0 ----
        {
            uint32_t ah[2][4], al[2][4];
            #pragma unroll
            for (int mt = 0; mt < 2; mt++) {
                uint32_t off = (wm * 32 + mt * 16 + arow) * 80 + acol16;
                ldsm4(ah[mt], XHU + off);
                ldsm4(al[mt], XLU + off);
            }
            #pragma unroll
            for (int nt = 0; nt < 10; nt++) {
                const int c0 = nt * 32 + wn * 8;
                uint32_t off = (c0 + brow2) * 80 + bcol16;
                uint32_t bh[2];
                ldsm2(bh, WHU + off);
                if (nt < 2) {
                    uint32_t bl[2];
                    ldsm2(bl, WLU + off);
                    #pragma unroll
                    for (int mt = 0; mt < 2; mt++) {
                        mma_f16(acc[mt][nt], ah[mt], bh);
                        mma_f16(acc[mt][nt], ah[mt], bl);
                        mma_f16(acc[mt][nt], al[mt], bh);
                    }
                } else {
                    #pragma unroll
                    for (int mt = 0; mt < 2; mt++)
                        mma_f16(acc[mt][nt], ah[mt], bh);
                }
            }
        }

        // ---- producer overlaps tensor drain ----
        if (ch + 1 < 8) stsX(ch + 1);   // consumes va (chunk ch+1)
        if (ch + 2 < 8) ldgX(ch + 2);   // refills va

        // ---- mma ks = 1 ----
        {
            uint32_t ah[2][4], al[2][4];
            #pragma unroll
            for (int mt = 0; mt < 2; mt++) {
                uint32_t off = (wm * 32 + mt * 16 + arow) * 80 + 32 + acol16;
                ldsm4(ah[mt], XHU + off);
                ldsm4(al[mt], XLU + off);
            }
            #pragma unroll
            for (int nt = 0; nt < 10; nt++) {
                const int c0 = nt * 32 + wn * 8;
                uint32_t off = (c0 + brow2) * 80 + 32 + bcol16;
                uint32_t bh[2];
                ldsm2(bh, WHU + off);
                if (nt < 2) {
                    uint32_t bl[2];
                    ldsm2(bl, WLU + off);
                    #pragma unroll
                    for (int mt = 0; mt < 2; mt++) {
                        mma_f16(acc[mt][nt], ah[mt], bh);
                        mma_f16(acc[mt][nt], ah[mt], bl);
                        mma_f16(acc[mt][nt], al[mt], bh);
                    }
                } else {
                    #pragma unroll
                    for (int mt = 0; mt < 2; mt++)
                        mma_f16(acc[mt][nt], ah[mt], bh);
                }
            }
        }

        if (ch + 2 < 8)      asm volatile("cp.async.wait_group 1;" ::: "memory");
        else if (ch + 1 < 8) asm volatile("cp.async.wait_group 0;" ::: "memory");
        __syncthreads();
    }

    // epilogue
    #pragma unroll
    for (int nt = 0; nt < 10; nt++) {
        const int c0 = nt * 32 + wn * 8 + 2 * (lane & 3);
        #pragma unroll
        for (int mt = 0; mt < 2; mt++) {
            const int r0 = rowbase + wm * 32 + mt * 16 + (lane >> 2);
            #pragma unroll
            for (int h2 = 0; h2 < 2; h2++) {
                const int r = r0 + h2 * 8;
                const float d0 = acc[mt][nt][h2 * 2 + 0];
                const float d1 = acc[mt][nt][h2 * 2 + 1];
                if (nt == 0) {
                    float v0 = d0 + bfv[c0], v1 = d1 + bfv[c0 + 1];
                    __half a0 = __float2half_rn(v0), a1 = __float2half_rn(v1);
                    __half b0 = __float2half_rn(v0 - __half2float(a0));
                    __half b1 = __float2half_rn(v1 - __half2float(a1));
                    *(uint32_t*)(g_f  + (size_t)r * CK + c0) = pack2(a0, a1);
                    *(uint32_t*)(g_fl + (size_t)r * CK + c0) = pack2(b0, b1);
                } else if (nt == 1) {
                    int c = c0 - 32;
                    float v0 = d0 + bgv[c], v1 = d1 + bgv[c + 1];
                    __half a0 = __float2half_rn(v0), a1 = __float2half_rn(v1);
                    __half b0 = __float2half_rn(v0 - __half2float(a0));
                    __half b1 = __float2half_rn(v1 - __half2float(a1));
                    *(uint32_t*)(g_g  + (size_t)r * CK + c) = pack2(a0, a1);
                    *(uint32_t*)(g_gl + (size_t)r * CK + c) = pack2(b0, b1);
                } else {
                    int c = c0 - 64;
                    int bb = r >> 12, n = r & 4095;
                    g_hT[((size_t)bb * C + c) * Nq + n]     = __float2half_rn(d0 + bhv[c]);
                    g_hT[((size_t)bb * C + c + 1) * Nq + n] = __float2half_rn(d1 + bhv[c + 1]);
                }
            }
        }
    }
}

// ===========================================================================
// Kernel 2: scores via fp16 3-term hi/lo (fp32-grade) + per-row max. (R14)
// ===========================================================================
constexpr int GH_OFF = 0, GL_OFF = 10240, FH_OFF = 20480, FL_OFF = 30720;
constexpr int SC_SMEM = 40960;

__global__ __launch_bounds__(256)
void score_kernel() {
    extern __shared__ char dsm[];
    const uint32_t base = smem_u32(dsm);

    const int t = threadIdx.x;
    const int lane = t & 31, wid = t >> 5;
    const int wm = wid >> 2, wn = wid & 3;
    const int mbase = blockIdx.y * 128, nbase = blockIdx.x * 128;
    const int bz = blockIdx.z;
    const size_t zoff = (size_t)bz * Nq * CK;

    #pragma unroll
    for (int i = 0; i < 2; i++) {
        int idx = t + i * 256;
        int r = idx >> 2, seg = idx & 3;
        uint32_t so = r * 80 + seg * 16;
        cp16(base + GH_OFF + so, g_g  + zoff + (size_t)(mbase + r) * CK + seg * 8);
        cp16(base + GL_OFF + so, g_gl + zoff + (size_t)(mbase + r) * CK + seg * 8);
        cp16(base + FH_OFF + so, g_f  + zoff + (size_t)(nbase + r) * CK + seg * 8);
        cp16(base + FL_OFF + so, g_fl + zoff + (size_t)(nbase + r) * CK + seg * 8);
    }
    cp_commit();
    asm volatile("cp.async.wait_group 0;" ::: "memory");
    __syncthreads();

    const int arow   = (lane & 7) + ((lane >> 3) & 1) * 8;
    const int acol16 = (lane >> 4) * 16;
    const int brow   = (lane >> 4) * 8 + (lane & 7);
    const int bcol16 = ((lane >> 3) & 1) * 16;

    float acc[4][4][4] = {};
    #pragma unroll
    for (int ks = 0; ks < 2; ks++) {
        uint32_t ah[4][4], al[4][4];
        #pragma unroll
        for (int mt = 0; mt < 4; mt++) {
            uint32_t off = (wm * 64 + mt * 16 + arow) * 80 + ks * 32 + acol16;
            ldsm4(ah[mt], base + GH_OFF + off);
            ldsm4(al[mt], base + GL_OFF + off);
        }
        #pragma unroll
        for (int j = 0; j < 2; j++) {
            uint32_t bh[4], bl[4];
            uint32_t off = (wn * 32 + j * 16 + brow) * 80 + ks * 32 + bcol16;
            ldsm4(bh, base + FH_OFF + off);
            ldsm4(bl, base + FL_OFF + off);
            #pragma unroll
            for (int sub = 0; sub < 2; sub++) {
                #pragma unroll
                for (int mt = 0; mt < 4; mt++) {
                    mma_f16(acc[mt][2 * j + sub], ah[mt], bh + sub * 2);
                    mma_f16(acc[mt][2 * j + sub], ah[mt], bl + sub * 2);
                    mma_f16(acc[mt][2 * j + sub], al[mt], bh + sub * 2);
                }
            }
        }
    }

    float* sout = g_s + (size_t)bz * Nq * Nq;
    #pragma unroll
    for (int mt = 0; mt < 4; mt++) {
        int r0 = mbase + wm * 64 + mt * 16 + (lane >> 2);
        float mx0 = -3.4e38f, mx1 = -3.4e38f;
        #pragma unroll
        for (int nt = 0; nt < 4; nt++) {
            int col = nbase + wn * 32 + nt * 8 + 2 * (lane & 3);
            float2 o0; o0.x = acc[mt][nt][0]; o0.y = acc[mt][nt][1];
            *(float2*)(sout + (size_t)r0 * Nq + col) = o0;
            float2 o1; o1.x = acc[mt][nt][2]; o1.y = acc[mt][nt][3];
            *(float2*)(sout + (size_t)(r0 + 8) * Nq + col) = o1;
            mx0 = fmaxf(mx0, fmaxf(o0.x, o0.y));
            mx1 = fmaxf(mx1, fmaxf(o1.x, o1.y));
        }
        mx0 = fmaxf(mx0, __shfl_xor_sync(0xffffffffu, mx0, 1));
        mx0 = fmaxf(mx0, __shfl_xor_sync(0xffffffffu, mx0, 2));
        mx1 = fmaxf(mx1, __shfl_xor_sync(0xffffffffu, mx1, 1));
        mx1 = fmaxf(mx1, __shfl_xor_sync(0xffffffffu, mx1, 2));
        if ((lane & 3) == 0) {
            atomicMax(&g_rowmaxE[bz * Nq + r0],     fenc(mx0));
            atomicMax(&g_rowmaxE[bz * Nq + r0 + 8], fenc(mx1));
        }
    }
}

// ===========================================================================
// Kernel 3: fused softmax + PV (fp16 mma) + residual.  BK=64 chunks. (R14)
// ===========================================================================
constexpr int PV_PITCH = 144;
constexpr int PV_A_ST  = 128 * PV_PITCH;            // 18432
constexpr int PV_B_ST  = 256 * PV_PITCH;            // 36864
constexpr int PV_A_OFF = 0;                         // 3 stages: 55296
constexpr int PV_B_OFF = 3 * PV_A_ST;               // 3 stages: 110592
constexpr int PV_Z_OFF = PV_B_OFF + 3 * PV_B_ST;    // 165888
constexpr int PV_SMEM  = PV_Z_OFF + 512;            // 166400
constexpr int NCH = Nq / 64;                        // 64

__global__ __launch_bounds__(512, 1)
void pv_kernel(const float* __restrict__ gamma_p,
               const float* __restrict__ x, float* __restrict__ y) {
    extern __shared__ char dsm[];
    const uint32_t base = smem_u32(dsm);
    float* zsm = (float*)(dsm + PV_Z_OFF);

    const int t = threadIdx.x;
    const int lane = t & 31, wid = t >> 5;
    const int wm = wid >> 3, wn = wid & 7;         // 2(M) x 8(N)
    const int qbase = blockIdx.x * 128;
    const int b = blockIdx.y;
    const float*  Pm  = g_s  + (size_t)b * Nq * Nq;
    const __half* hTb = g_hT + (size_t)b * C * Nq;

    if (t < 128) zsm[t] = 0.f;

    const int tr = t >> 2;           // 0..127: one q-row per thread
    const int cb = (t & 3) * 16;     // 16 contiguous cols per thread

    const int arow   = (lane & 7) + ((lane >> 3) & 1) * 8;
    const int acol16 = (lane >> 4) * 16;
    const int brow   = (lane >> 4) * 8 + (lane & 7);
    const int bcol16 = ((lane >> 3) & 1) * 16;

    const float rm = fdec(g_rowmaxE[b * Nq + qbase + tr]);

    float4 va[4];
    float zp = 0.f;

    auto ldgA = [&](int chunk) {
        const float* bp = Pm + (size_t)(qbase + tr) * Nq + chunk * 64 + cb;
        #pragma unroll
        for (int i = 0; i < 4; i++)
            va[i] = *(const float4*)(bp + i * 4);
    };
    auto expSts = [&](int chunk) {
        char* Ad = dsm + PV_A_OFF + (chunk % 3) * PV_A_ST;
        #pragma unroll
        for (int i = 0; i < 4; i++) {
            float p0 = __expf(va[i].x - rm);
            float p1 = __expf(va[i].y - rm);
            float p2 = __expf(va[i].z - rm);
            float p3 = __expf(va[i].w - rm);
            zp += (p0 + p1) + (p2 + p3);
            uint2 u;
            u.x = pack2(__float2half_rn(p0), __float2half_rn(p1));
            u.y = pack2(__float2half_rn(p2), __float2half_rn(p3));
            *(uint2*)(Ad + tr * PV_PITCH + (cb + i * 4) * 2) = u;
        }
    };
    auto cpB = [&](int chunk) {
        uint32_t Bd = base + PV_B_OFF + (chunk % 3) * PV_B_ST;
        #pragma unroll
        for (int i = 0; i < 4; i++) {
            int idx = t + i * 512;
            int r = idx >> 3, seg = idx & 7;
            cp16(Bd + r * PV_PITCH + seg * 16, hTb + (size_t)r * Nq + chunk * 64 + seg * 8);
        }
        cp_commit();
    };

    // prologue
    cpB(0); cpB(1);
    ldgA(0);
    expSts(0);
    ldgA(1);
    asm volatile("cp.async.wait_group 1;" ::: "memory");
    __syncthreads();

    float acc[4][4][4] = {};   // warp tile 64(M) x 32(N)

    for (int c = 0; c < NCH; c++) {
        if (c + 2 < NCH) cpB(c + 2);

        const uint32_t AsbU = base + PV_A_OFF + (c % 3) * PV_A_ST;
        const uint32_t BsbU = base + PV_B_OFF + (c % 3) * PV_B_ST;

        #pragma unroll
        for (int ks = 0; ks < 2; ks++) {
            uint32_t af[4][4];
            #pragma unroll
            for (int mt = 0; mt < 4; mt++)
                ldsm4(af[mt], AsbU + (wm * 64 + mt * 16 + arow) * PV_PITCH + ks * 32 + acol16);
            #pragma unroll
            for (int j = 0; j < 2; j++) {
                uint32_t bf[4];
                ldsm4(bf, BsbU + (wn * 32 + j * 16 + brow) * PV_PITCH + ks * 32 + bcol16);
                #pragma unroll
                for (int mt = 0; mt < 4; mt++) {
                    mma_f16(acc[mt][2 * j + 0], af[mt], bf + 0);
                    mma_f16(acc[mt][2 * j + 1], af[mt], bf + 2);
                }
            }
        }

        if (c + 1 < NCH) expSts(c + 1);
        if (c + 2 < NCH) ldgA(c + 2);

        #pragma unroll
        for (int ks = 2; ks < 4; ks++) {
            uint32_t af[4][4];
            #pragma unroll
            for (int mt = 0; mt < 4; mt++)
                ldsm4(af[mt], AsbU + (wm * 64 + mt * 16 + arow) * PV_PITCH + ks * 32 + acol16);
            #pragma unroll
            for (int j = 0; j < 2; j++) {
                uint32_t bf[4];
                ldsm4(bf, BsbU + (wn * 32 + j * 16 + brow) * PV_PITCH + ks * 32 + bcol16);
                #pragma unroll
                for (int mt = 0; mt < 4; mt++) {
                    mma_f16(acc[mt][2 * j + 0], af[mt], bf + 0);
                    mma_f16(acc[mt][2 * j + 1], af[mt], bf + 2);
                }
            }
        }

        if (c + 2 < NCH)      asm volatile("cp.async.wait_group 1;" ::: "memory");
        else if (c + 1 < NCH) asm volatile("cp.async.wait_group 0;" ::: "memory");
        __syncthreads();
    }

    atomicAdd(&zsm[tr], zp);
    __syncthreads();

    const float gam = __ldg(gamma_p);
    #pragma unroll
    for (int mt = 0; mt < 4; mt++) {
        int row0 = wm * 64 + mt * 16 + (lane >> 2);
        float sc0 = gam / zsm[row0];
        float sc1 = gam / zsm[row0 + 8];
        #pragma unroll
        for (int nt = 0; nt < 4; nt++) {
            int col = wn * 32 + nt * 8 + 2 * (lane & 3);
            size_t bo = ((size_t)b * Nq + qbase + row0) * C + col;
            float2 x0 = *(const float2*)(x + bo);
            float2 o0;
            o0.x = sc0 * acc[mt][nt][0] + x0.x;
            o0.y = sc0 * acc[mt][nt][1] + x0.y;
            *(float2*)(y + bo) = o0;
            size_t bo2 = bo + 8 * (size_t)C;
            float2 x1 = *(const float2*)(x + bo2);
            float2 o1;
            o1.x = sc1 * acc[mt][nt][2] + x1.x;
            o1.y = sc1 * acc[mt][nt][3] + x1.y;
            *(float2*)(y + bo2) = o1;
        }
    }
}

// ===========================================================================
extern "C" void kernel_launch(void* const* d_in, const int* in_sizes, int n_in,
                              void* d_out, int out_size) {
    (void)in_sizes; (void)n_in; (void)out_size;
    const float* x     = (const float*)d_in[0];
    const float* Wf    = (const float*)d_in[1];
    const float* bf    = (const float*)d_in[2];
    const float* Wg    = (const float*)d_in[3];
    const float* bg    = (const float*)d_in[4];
    const float* Wh    = (const float*)d_in[5];
    const float* bh    = (const float*)d_in[6];
    const float* gamma = (const float*)d_in[7];
    float* y = (float*)d_out;

    cudaFuncSetAttribute(proj_kernel, cudaFuncAttributeMaxDynamicSharedMemorySize, PJ_SMEM);
    cudaFuncSetAttribute(score_kernel, cudaFuncAttributeMaxDynamicSharedMemorySize, SC_SMEM);
    cudaFuncSetAttribute(pv_kernel, cudaFuncAttributeMaxDynamicSharedMemorySize, PV_SMEM);

    wtrans_kernel<<<320, 256>>>(Wf, Wg, Wh);
    proj_kernel<<<(Bb * Nq) / 128, 512, PJ_SMEM>>>(x, bf, bg, bh);
    score_kernel<<<dim3(Nq / 128, Nq / 128, Bb), 256, SC_SMEM>>>();
    pv_kernel<<<dim3(Nq / 128, Bb), 512, PV_SMEM>>>(gamma, x, y);
}

// round 16
// speedup vs baseline: 1.0530x; 1.0530x over previous
#include <cuda_runtime.h>
#include <cuda_fp16.h>
#include <cstdint>

// Problem dims (fixed by dataset)
constexpr int Bb = 4;      // batch
constexpr int Nq = 4096;   // H*W
constexpr int C  = 256;    // channels
constexpr int CK = 32;     // key/query channels

// Scratch in __device__ globals (allocation-free rule)
__device__ __half g_f [(size_t)Bb * Nq * CK];            // keys   (fp16 hi)
__device__ __half g_fl[(size_t)Bb * Nq * CK];            // keys   (fp16 lo residual)
__device__ __half g_g [(size_t)Bb * Nq * CK];            // queries(fp16 hi)
__device__ __half g_gl[(size_t)Bb * Nq * CK];            // queries(fp16 lo residual)
__device__ __half g_hT[(size_t)Bb * C * Nq];             // values, transposed, fp16
__device__ __half g_p [(size_t)Bb * Nq * Nq];            // P = exp(s - m_tile), fp16 (128 MB)
__device__ float  g_mtile[(size_t)Bb * Nq * 128];        // per-(row, 32col-tile) max (8 MB)
__device__ __half g_WT  [320 * 256];                     // [Wf|Wg|Wh]^T fp16 hi
__device__ __half g_WTlo[64 * 256];                      // lo residual for f,g cols
__device__ unsigned int g_rowmaxE[Bb * Nq];              // encoded global row maxes

__device__ __forceinline__ uint32_t smem_u32(const void* p) {
    return (uint32_t)__cvta_generic_to_shared(p);
}
__device__ __forceinline__ void cp16(uint32_t s, const void* g) {
    asm volatile("cp.async.cg.shared.global [%0], [%1], 16;" :: "r"(s), "l"(g));
}
__device__ __forceinline__ void cp_commit() {
    asm volatile("cp.async.commit_group;" ::: "memory");
}
__device__ __forceinline__ uint32_t pack2(__half a, __half b) {
    __half2 h = __halves2half2(a, b);
    return *(uint32_t*)&h;
}
__device__ __forceinline__ void mma_f16(float* d, const uint32_t* a, const uint32_t* b) {
    asm volatile(
        "mma.sync.aligned.m16n8k16.row.col.f32.f16.f16.f32 "
        "{%0,%1,%2,%3}, {%4,%5,%6,%7}, {%8,%9}, {%0,%1,%2,%3};"
        : "+f"(d[0]), "+f"(d[1]), "+f"(d[2]), "+f"(d[3])
        : "r"(a[0]), "r"(a[1]), "r"(a[2]), "r"(a[3]), "r"(b[0]), "r"(b[1]));
}
__device__ __forceinline__ void ldsm4(uint32_t* r, uint32_t a) {
    asm volatile("ldmatrix.sync.aligned.m8n8.x4.shared.b16 {%0,%1,%2,%3}, [%4];"
        : "=r"(r[0]), "=r"(r[1]), "=r"(r[2]), "=r"(r[3]) : "r"(a));
}
__device__ __forceinline__ void ldsm2(uint32_t* r, uint32_t a) {
    asm volatile("ldmatrix.sync.aligned.m8n8.x2.shared.b16 {%0,%1}, [%2];"
        : "=r"(r[0]), "=r"(r[1]) : "r"(a));
}
// monotone float<->uint encoding for atomicMax over signed floats
__device__ __forceinline__ uint32_t fenc(float f) {
    uint32_t u = __float_as_uint(f);
    return (u & 0x80000000u) ? ~u : (u | 0x80000000u);
}
__device__ __forceinline__ float fdec(uint32_t e) {
    uint32_t u = (e & 0x80000000u) ? (e & 0x7fffffffu) : ~e;
    return __uint_as_float(u);
}

// ===========================================================================
// Kernel 0: W pre-transpose + fp16 hi/lo pre-split; init row-max table.
// ===========================================================================
__global__ void wtrans_kernel(const float* __restrict__ Wf,
                              const float* __restrict__ Wg,
                              const float* __restrict__ Wh) {
    int idx = blockIdx.x * 256 + threadIdx.x;       // 320*256 total
    if (idx < Bb * Nq) g_rowmaxE[idx] = 0u;         // < any real encoded value
    int n = idx >> 8, k = idx & 255;
    float w;
    if (n < 32)       w = Wf[k * CK + n];
    else if (n < 64)  w = Wg[k * CK + (n - 32)];
    else              w = Wh[k * C + (n - 64)];
    __half hi = __float2half_rn(w);
    g_WT[n * 256 + k] = hi;
    if (n < 64)
        g_WTlo[n * 256 + k] = __float2half_rn(w - __half2float(hi));
}

// ===========================================================================
// Kernel 1: fused projections, fp16 mma. CTA 64 rows x 320 cols, K=256. (R14)
// ===========================================================================
constexpr int XH_OFF = 0;          // 64*80   = 5120
constexpr int XL_OFF = 5120;       // 5120
constexpr int WH_OFF = 10240;      // 320*80  = 25600
constexpr int WL_OFF = 35840;      // 64*80   = 5120
constexpr int PJ_SMEM = 40960;

__global__ __launch_bounds__(256, 2)
void proj_kernel(const float* __restrict__ x,
                 const float* __restrict__ bfv, const float* __restrict__ bgv,
                 const float* __restrict__ bhv) {
    extern __shared__ char dsm[];
    const uint32_t base = smem_u32(dsm);

    const int t = threadIdx.x;
    const int lane = t & 31, wid = t >> 5;
    const int wm = wid >> 2, wn = wid & 3;
    const int rowbase = blockIdx.x * 64;

    const int arow   = (lane & 7) + ((lane >> 3) & 1) * 8;
    const int acol16 = (lane >> 4) * 16;
    const int brow2  = lane & 7;
    const int bcol16 = ((lane >> 3) & 1) * 16;

    float acc[2][10][4] = {};
    float4 va[2], vb[2];

    auto ldgX = [&](int ch, float4* v) {
        #pragma unroll
        for (int i = 0; i < 2; i++) {
            int idx = t + i * 256;
            int r = idx >> 3, c4 = (idx & 7) * 4;
            v[i] = *(const float4*)(x + (size_t)(rowbase + r) * C + ch * 32 + c4);
        }
    };
    auto stsX = [&](const float4* v) {
        #pragma unroll
        for (int i = 0; i < 2; i++) {
            int idx = t + i * 256;
            int r = idx >> 3, c4 = (idx & 7) * 4;
            float f[4] = {v[i].x, v[i].y, v[i].z, v[i].w};
            __half h[4], l[4];
            #pragma unroll
            for (int e = 0; e < 4; e++) {
                h[e] = __float2half_rn(f[e]);
                l[e] = __float2half_rn(f[e] - __half2float(h[e]));
            }
            uint2 uh, ul;
            uh.x = pack2(h[0], h[1]); uh.y = pack2(h[2], h[3]);
            ul.x = pack2(l[0], l[1]); ul.y = pack2(l[2], l[3]);
            *(uint2*)(dsm + XH_OFF + r * 80 + c4 * 2) = uh;
            *(uint2*)(dsm + XL_OFF + r * 80 + c4 * 2) = ul;
        }
    };

    ldgX(0, va);
    for (int ch = 0; ch < 8; ch++) {
        __syncthreads();            // prev chunk's mma reads done
        stsX(va);
        if (ch < 7) ldgX(ch + 1, vb);
        #pragma unroll
        for (int i = 0; i < 5; i++) {          // W hi: 1280 cp16
            int idx = t + i * 256;
            int r = idx >> 2, seg = idx & 3;
            cp16(base + WH_OFF + r * 80 + seg * 16, g_WT + r * 256 + ch * 32 + seg * 8);
        }
        {
            int r = t >> 2, seg = t & 3;       // W lo: 256 cp16
            cp16(base + WL_OFF + r * 80 + seg * 16, g_WTlo + r * 256 + ch * 32 + seg * 8);
        }
        cp_commit();
        asm volatile("cp.async.wait_group 0;" ::: "memory");
        __syncthreads();

        #pragma unroll
        for (int ks = 0; ks < 2; ks++) {
            uint32_t ah[2][4], al[2][4];
            #pragma unroll
            for (int mt = 0; mt < 2; mt++) {
                uint32_t off = (wm * 32 + mt * 16 + arow) * 80 + ks * 32 + acol16;
                ldsm4(ah[mt], base + XH_OFF + off);
                ldsm4(al[mt], base + XL_OFF + off);
            }
            #pragma unroll
            for (int nt = 0; nt < 10; nt++) {
                const int c0 = nt * 32 + wn * 8;
                uint32_t off = (c0 + brow2) * 80 + ks * 32 + bcol16;
                uint32_t bh[2];
                ldsm2(bh, base + WH_OFF + off);
                if (nt < 2) {
                    uint32_t bl[2];
                    ldsm2(bl, base + WL_OFF + off);
                    #pragma unroll
                    for (int mt = 0; mt < 2; mt++) {
                        mma_f16(acc[mt][nt], ah[mt], bh);
                        mma_f16(acc[mt][nt], ah[mt], bl);
                        mma_f16(acc[mt][nt], al[mt], bh);
                    }
                } else {
                    #pragma unroll
                    for (int mt = 0; mt < 2; mt++)
                        mma_f16(acc[mt][nt], ah[mt], bh);
                }
            }
        }
        va[0] = vb[0]; va[1] = vb[1];
    }

    // epilogue
    #pragma unroll
    for (int nt = 0; nt < 10; nt++) {
        const int c0 = nt * 32 + wn * 8 + 2 * (lane & 3);
        #pragma unroll
        for (int mt = 0; mt < 2; mt++) {
            const int r0 = rowbase + wm * 32 + mt * 16 + (lane >> 2);
            #pragma unroll
            for (int h2 = 0; h2 < 2; h2++) {
                const int r = r0 + h2 * 8;
                const float d0 = acc[mt][nt][h2 * 2 + 0];
                const float d1 = acc[mt][nt][h2 * 2 + 1];
                if (nt == 0) {
                    float v0 = d0 + bfv[c0], v1 = d1 + bfv[c0 + 1];
                    __half a0 = __float2half_rn(v0), a1 = __float2half_rn(v1);
                    __half b0 = __float2half_rn(v0 - __half2float(a0));
                    __half b1 = __float2half_rn(v1 - __half2float(a1));
                    *(uint32_t*)(g_f  + (size_t)r * CK + c0) = pack2(a0, a1);
                    *(uint32_t*)(g_fl + (size_t)r * CK + c0) = pack2(b0, b1);
                } else if (nt == 1) {
                    int c = c0 - 32;
                    float v0 = d0 + bgv[c], v1 = d1 + bgv[c + 1];
                    __half a0 = __float2half_rn(v0), a1 = __float2half_rn(v1);
                    __half b0 = __float2half_rn(v0 - __half2float(a0));
                    __half b1 = __float2half_rn(v1 - __half2float(a1));
                    *(uint32_t*)(g_g  + (size_t)r * CK + c) = pack2(a0, a1);
                    *(uint32_t*)(g_gl + (size_t)r * CK + c) = pack2(b0, b1);
                } else {
                    int c = c0 - 64;
                    int bb = r >> 12, n = r & 4095;
                    g_hT[((size_t)bb * C + c) * Nq + n]     = __float2half_rn(d0 + bhv[c]);
                    g_hT[((size_t)bb * C + c + 1) * Nq + n] = __float2half_rn(d1 + bhv[c + 1]);
                }
            }
        }
    }
}

// ===========================================================================
// Kernel 2: scores (fp16 3-term hi/lo) -> tile-local softmax factoring.
//   Stores p = fp16(exp(s - m_tile)), m_tile per (row, 32col warp tile),
//   and global row max via atomicMax.
// ===========================================================================
constexpr int GH_OFF = 0, GL_OFF = 10240, FH_OFF = 20480, FL_OFF = 30720;
constexpr int SC_SMEM = 40960;

__global__ __launch_bounds__(256)
void score_kernel() {
    extern __shared__ char dsm[];
    const uint32_t base = smem_u32(dsm);

    const int t = threadIdx.x;
    const int lane = t & 31, wid = t >> 5;
    const int wm = wid >> 2, wn = wid & 3;
    const int mbase = blockIdx.y * 128, nbase = blockIdx.x * 128;
    const int bz = blockIdx.z;
    const size_t zoff = (size_t)bz * Nq * CK;

    #pragma unroll
    for (int i = 0; i < 2; i++) {
        int idx = t + i * 256;
        int r = idx >> 2, seg = idx & 3;
        uint32_t so = r * 80 + seg * 16;
        cp16(base + GH_OFF + so, g_g  + zoff + (size_t)(mbase + r) * CK + seg * 8);
        cp16(base + GL_OFF + so, g_gl + zoff + (size_t)(mbase + r) * CK + seg * 8);
        cp16(base + FH_OFF + so, g_f  + zoff + (size_t)(nbase + r) * CK + seg * 8);
        cp16(base + FL_OFF + so, g_fl + zoff + (size_t)(nbase + r) * CK + seg * 8);
    }
    cp_commit();
    asm volatile("cp.async.wait_group 0;" ::: "memory");
    __syncthreads();

    const int arow   = (lane & 7) + ((lane >> 3) & 1) * 8;
    const int acol16 = (lane >> 4) * 16;
    const int brow   = (lane >> 4) * 8 + (lane & 7);
    const int bcol16 = ((lane >> 3) & 1) * 16;

    float acc[4][4][4] = {};
    #pragma unroll
    for (int ks = 0; ks < 2; ks++) {
        uint32_t ah[4][4], al[4][4];
        #pragma unroll
        for (int mt = 0; mt < 4; mt++) {
            uint32_t off = (wm * 64 + mt * 16 + arow) * 80 + ks * 32 + acol16;
            ldsm4(ah[mt], base + GH_OFF + off);
            ldsm4(al[mt], base + GL_OFF + off);
        }
        #pragma unroll
        for (int j = 0; j < 2; j++) {
            uint32_t bh[4], bl[4];
            uint32_t off = (wn * 32 + j * 16 + brow) * 80 + ks * 32 + bcol16;
            ldsm4(bh, base + FH_OFF + off);
            ldsm4(bl, base + FL_OFF + off);
            #pragma unroll
            for (int sub = 0; sub < 2; sub++) {
                #pragma unroll
                for (int mt = 0; mt < 4; mt++) {
                    mma_f16(acc[mt][2 * j + sub], ah[mt], bh + sub * 2);
                    mma_f16(acc[mt][2 * j + sub], ah[mt], bl + sub * 2);
                    mma_f16(acc[mt][2 * j + sub], al[mt], bh + sub * 2);
                }
            }
        }
    }

    __half* pout = g_p + (size_t)bz * Nq * Nq;
    const int tix = blockIdx.x * 4 + wn;      // 32col tile index (0..127)
    #pragma unroll
    for (int mt = 0; mt < 4; mt++) {
        int r0 = mbase + wm * 64 + mt * 16 + (lane >> 2);
        float mx0 = -3.4e38f, mx1 = -3.4e38f;
        #pragma unroll
        for (int nt = 0; nt < 4; nt++) {
            mx0 = fmaxf(mx0, fmaxf(acc[mt][nt][0], acc[mt][nt][1]));
            mx1 = fmaxf(mx1, fmaxf(acc[mt][nt][2], acc[mt][nt][3]));
        }
        mx0 = fmaxf(mx0, __shfl_xor_sync(0xffffffffu, mx0, 1));
        mx0 = fmaxf(mx0, __shfl_xor_sync(0xffffffffu, mx0, 2));
        mx1 = fmaxf(mx1, __shfl_xor_sync(0xffffffffu, mx1, 1));
        mx1 = fmaxf(mx1, __shfl_xor_sync(0xffffffffu, mx1, 2));
        if ((lane & 3) == 0) {
            atomicMax(&g_rowmaxE[bz * Nq + r0],     fenc(mx0));
            atomicMax(&g_rowmaxE[bz * Nq + r0 + 8], fenc(mx1));
            g_mtile[((size_t)bz * Nq + r0)     * 128 + tix] = mx0;
            g_mtile[((size_t)bz * Nq + r0 + 8) * 128 + tix] = mx1;
        }
        #pragma unroll
        for (int nt = 0; nt < 4; nt++) {
            int col = nbase + wn * 32 + nt * 8 + 2 * (lane & 3);
            *(uint32_t*)(pout + (size_t)r0 * Nq + col) =
                pack2(__float2half_rn(__expf(acc[mt][nt][0] - mx0)),
                      __float2half_rn(__expf(acc[mt][nt][1] - mx0)));
            *(uint32_t*)(pout + (size_t)(r0 + 8) * Nq + col) =
                pack2(__float2half_rn(__expf(acc[mt][nt][2] - mx1)),
                      __float2half_rn(__expf(acc[mt][nt][3] - mx1)));
        }
    }
}

// ===========================================================================
// Kernel 3: fused softmax + PV (fp16 mma) + residual.  BK=64 chunks.
//   A-producer: load fp16 p + m_tile, rescale by exp(m_tile - rowmax) (one
//   MUFU per thread per chunk), accumulate Z, STS. (R14 pipeline shape.)
// ===========================================================================
constexpr int PV_PITCH = 144;
constexpr int PV_A_ST  = 128 * PV_PITCH;            // 18432
constexpr int PV_B_ST  = 256 * PV_PITCH;            // 36864
constexpr int PV_A_OFF = 0;                         // 3 stages: 55296
constexpr int PV_B_OFF = 3 * PV_A_ST;               // 3 stages: 110592
constexpr int PV_Z_OFF = PV_B_OFF + 3 * PV_B_ST;    // 165888
constexpr int PV_SMEM  = PV_Z_OFF + 512;            // 166400
constexpr int NCH = Nq / 64;                        // 64

__global__ __launch_bounds__(512, 1)
void pv_kernel(const float* __restrict__ gamma_p,
               const float* __restrict__ x, float* __restrict__ y) {
    extern __shared__ char dsm[];
    const uint32_t base = smem_u32(dsm);
    float* zsm = (float*)(dsm + PV_Z_OFF);

    const int t = threadIdx.x;
    const int lane = t & 31, wid = t >> 5;
    const int wm = wid >> 3, wn = wid & 7;         // 2(M) x 8(N)
    const int qbase = blockIdx.x * 128;
    const int b = blockIdx.y;
    const __half* Pp  = g_p  + (size_t)b * Nq * Nq;
    const __half* hTb = g_hT + (size_t)b * C * Nq;

    if (t < 128) zsm[t] = 0.f;

    const int tr = t >> 2;           // 0..127: one q-row per thread
    const int cb = (t & 3) * 16;     // 16 contiguous cols per thread
    const int subsel = cb >> 5;      // 0 or 1: which 32-col subtile

    const int arow   = (lane & 7) + ((lane >> 3) & 1) * 8;
    const int acol16 = (lane >> 4) * 16;
    const int brow   = (lane >> 4) * 8 + (lane & 7);
    const int bcol16 = ((lane >> 3) & 1) * 16;

    const float rm = fdec(g_rowmaxE[b * Nq + qbase + tr]);
    const float* mrow = g_mtile + ((size_t)b * Nq + qbase + tr) * 128;

    uint4 va16[2];
    float vmsub;
    float zp = 0.f;

    auto ldgA = [&](int chunk) {
        const __half* bp = Pp + (size_t)(qbase + tr) * Nq + chunk * 64 + cb;
        va16[0] = *(const uint4*)(bp);
        va16[1] = *(const uint4*)(bp + 8);
        vmsub = mrow[2 * chunk + subsel];
    };
    auto scaleSts = [&](int chunk) {
        char* Ad = dsm + PV_A_OFF + (chunk % 3) * PV_A_ST;
        float scf = __expf(vmsub - rm);
        __half2 sc2 = __float2half2_rn(scf);
        uint4 out[2];
        #pragma unroll
        for (int i = 0; i < 2; i++) {
            const uint32_t* pu = (const uint32_t*)&va16[i];
            uint32_t* ou = (uint32_t*)&out[i];
            #pragma unroll
            for (int j = 0; j < 4; j++) {
                __half2 h = *(const __half2*)&pu[j];
                __half2 r = __hmul2(h, sc2);
                ou[j] = *(uint32_t*)&r;
                float2 f = __half22float2(r);
                zp += f.x + f.y;
            }
        }
        *(uint4*)(Ad + tr * PV_PITCH + cb * 2)      = out[0];
        *(uint4*)(Ad + tr * PV_PITCH + cb * 2 + 16) = out[1];
    };
    auto cpB = [&](int chunk) {
        uint32_t Bd = base + PV_B_OFF + (chunk % 3) * PV_B_ST;
        #pragma unroll
        for (int i = 0; i < 4; i++) {
            int idx = t + i * 512;
            int r = idx >> 3, seg = idx & 7;
            cp16(Bd + r * PV_PITCH + seg * 16, hTb + (size_t)r * Nq + chunk * 64 + seg * 8);
        }
        cp_commit();
    };

    // prologue
    cpB(0); cpB(1);
    ldgA(0);
    scaleSts(0);
    ldgA(1);
    asm volatile("cp.async.wait_group 1;" ::: "memory");
    __syncthreads();

    float acc[4][4][4] = {};   // warp tile 64(M) x 32(N)

    for (int c = 0; c < NCH; c++) {
        if (c + 2 < NCH) cpB(c + 2);

        const uint32_t AsbU = base + PV_A_OFF + (c % 3) * PV_A_ST;
        const uint32_t BsbU = base + PV_B_OFF + (c % 3) * PV_B_ST;

        #pragma unroll
        for (int ks = 0; ks < 2; ks++) {
            uint32_t af[4][4];
            #pragma unroll
            for (int mt = 0; mt < 4; mt++)
                ldsm4(af[mt], AsbU + (wm * 64 + mt * 16 + arow) * PV_PITCH + ks * 32 + acol16);
            #pragma unroll
            for (int j = 0; j < 2; j++) {
                uint32_t bf[4];
                ldsm4(bf, BsbU + (wn * 32 + j * 16 + brow) * PV_PITCH + ks * 32 + bcol16);
                #pragma unroll
                for (int mt = 0; mt < 4; mt++) {
                    mma_f16(acc[mt][2 * j + 0], af[mt], bf + 0);
                    mma_f16(acc[mt][2 * j + 1], af[mt], bf + 2);
                }
            }
        }

        if (c + 1 < NCH) scaleSts(c + 1);
        if (c + 2 < NCH) ldgA(c + 2);

        #pragma unroll
        for (int ks = 2; ks < 4; ks++) {
            uint32_t af[4][4];
            #pragma unroll
            for (int mt = 0; mt < 4; mt++)
                ldsm4(af[mt], AsbU + (wm * 64 + mt * 16 + arow) * PV_PITCH + ks * 32 + acol16);
            #pragma unroll
            for (int j = 0; j < 2; j++) {
                uint32_t bf[4];
                ldsm4(bf, BsbU + (wn * 32 + j * 16 + brow) * PV_PITCH + ks * 32 + bcol16);
                #pragma unroll
                for (int mt = 0; mt < 4; mt++) {
                    mma_f16(acc[mt][2 * j + 0], af[mt], bf + 0);
                    mma_f16(acc[mt][2 * j + 1], af[mt], bf + 2);
                }
            }
        }

        if (c + 2 < NCH)      asm volatile("cp.async.wait_group 1;" ::: "memory");
        else if (c + 1 < NCH) asm volatile("cp.async.wait_group 0;" ::: "memory");
        __syncthreads();
    }

    atomicAdd(&zsm[tr], zp);
    __syncthreads();

    const float gam = __ldg(gamma_p);
    #pragma unroll
    for (int mt = 0; mt < 4; mt++) {
        int row0 = wm * 64 + mt * 16 + (lane >> 2);
        float sc0 = gam / zsm[row0];
        float sc1 = gam / zsm[row0 + 8];
        #pragma unroll
        for (int nt = 0; nt < 4; nt++) {
            int col = wn * 32 + nt * 8 + 2 * (lane & 3);
            size_t bo = ((size_t)b * Nq + qbase + row0) * C + col;
            float2 x0 = *(const float2*)(x + bo);
            float2 o0;
            o0.x = sc0 * acc[mt][nt][0] + x0.x;
            o0.y = sc0 * acc[mt][nt][1] + x0.y;
            *(float2*)(y + bo) = o0;
            size_t bo2 = bo + 8 * (size_t)C;
            float2 x1 = *(const float2*)(x + bo2);
            float2 o1;
            o1.x = sc1 * acc[mt][nt][2] + x1.x;
            o1.y = sc1 * acc[mt][nt][3] + x1.y;
            *(float2*)(y + bo2) = o1;
        }
    }
}

// ===========================================================================
extern "C" void kernel_launch(void* const* d_in, const int* in_sizes, int n_in,
                              void* d_out, int out_size) {
    (void)in_sizes; (void)n_in; (void)out_size;
    const float* x     = (const float*)d_in[0];
    const float* Wf    = (const float*)d_in[1];
    const float* bf    = (const float*)d_in[2];
    const float* Wg    = (const float*)d_in[3];
    const float* bg    = (const float*)d_in[4];
    const float* Wh    = (const float*)d_in[5];
    const float* bh    = (const float*)d_in[6];
    const float* gamma = (const float*)d_in[7];
    float* y = (float*)d_out;

    cudaFuncSetAttribute(proj_kernel, cudaFuncAttributeMaxDynamicSharedMemorySize, PJ_SMEM);
    cudaFuncSetAttribute(score_kernel, cudaFuncAttributeMaxDynamicSharedMemorySize, SC_SMEM);
    cudaFuncSetAttribute(pv_kernel, cudaFuncAttributeMaxDynamicSharedMemorySize, PV_SMEM);

    wtrans_kernel<<<320, 256>>>(Wf, Wg, Wh);
    proj_kernel<<<(Bb * Nq) / 64, 256, PJ_SMEM>>>(x, bf, bg, bh);
    score_kernel<<<dim3(Nq / 128, Nq / 128, Bb), 256, SC_SMEM>>>();
    pv_kernel<<<dim3(Nq / 128, Bb), 512, PV_SMEM>>>(gamma, x, y);
}